// round 6
// baseline (speedup 1.0000x reference)
#include <cuda_runtime.h>

// out[r] = dot(x[r], w_avg) + b_avg   (mean of linear == linear of mean)
//
// Single fused kernel. Three measured fixes combined:
//  - x float4 loads issued FIRST (R5: hides param-fetch latency behind DRAM)
//  - per-warp param reduction + __syncwarp (warp-local ~23cyc; no CTA-wide
//    BAR coupling that cost R2/R5 their occupancy)
//  - __launch_bounds__(256, 8): force 32 regs -> 8 CTAs/SM residency, the
//    configuration that produced the best measured stream (R1: 83.7% occ,
//    74% DRAM, 29.2us). Coefs live in per-warp smem, not registers.
// Body: one thread per ROW PAIR (80B = 5 x float4, 16B aligned), full grid,
// streaming hints on x and out (strictly single-use, 176MB).

__global__ __launch_bounds__(256, 8) void forest_warpsmem_kernel(
    const float4* __restrict__ x4,   // x as float4; 5 per row-pair
    const float*  __restrict__ W,    // [10, 1, 10]
    const float*  __restrict__ b,    // [10, 1]
    float2* __restrict__ out2,       // out as float2; 1 per row-pair
    int npairs) {
    __shared__ float sc[8][11];      // per-warp coefficient slice

    const int warp = threadIdx.x >> 5;
    const int lane = threadIdx.x & 31;

    const int t = blockIdx.x * blockDim.x + threadIdx.x;
    const bool active = (t < npairs);
    const int tc = active ? t : (npairs - 1);   // clamp: tail lanes re-read last pair

    // ---- 1. x loads first: go to DRAM immediately, ~600cyc to hide ----
    const float4* p = x4 + (size_t)tc * 5;
    float4 v0 = __ldcs(p + 0);
    float4 v1 = __ldcs(p + 1);
    float4 v2 = __ldcs(p + 2);
    float4 v3 = __ldcs(p + 3);
    float4 v4 = __ldcs(p + 4);

    // ---- 2. per-warp param reduction (440B, L1-resident after 1st CTA) ----
    if (lane < 11) {
        float s = 0.f;
        if (lane < 10) {
#pragma unroll
            for (int e = 0; e < 10; ++e) s += W[e * 10 + lane];
        } else {
#pragma unroll
            for (int e = 0; e < 10; ++e) s += b[e];
        }
        sc[warp][lane] = s * 0.1f;
    }
    __syncwarp();                    // warp-local; no cross-warp coupling

    const float* c = sc[warp];       // broadcast LDS reads, conflict-free

    // Row 0 = {v0.xyzw, v1.xyzw, v2.xy}
    float r0 = v0.x * c[0];
    r0 = fmaf(v0.y, c[1], r0);
    r0 = fmaf(v0.z, c[2], r0);
    r0 = fmaf(v0.w, c[3], r0);
    r0 = fmaf(v1.x, c[4], r0);
    r0 = fmaf(v1.y, c[5], r0);
    r0 = fmaf(v1.z, c[6], r0);
    r0 = fmaf(v1.w, c[7], r0);
    r0 = fmaf(v2.x, c[8], r0);
    r0 = fmaf(v2.y, c[9], r0);

    // Row 1 = {v2.zw, v3.xyzw, v4.xyzw}
    float r1 = v2.z * c[0];
    r1 = fmaf(v2.w, c[1], r1);
    r1 = fmaf(v3.x, c[2], r1);
    r1 = fmaf(v3.y, c[3], r1);
    r1 = fmaf(v3.z, c[4], r1);
    r1 = fmaf(v3.w, c[5], r1);
    r1 = fmaf(v4.x, c[6], r1);
    r1 = fmaf(v4.y, c[7], r1);
    r1 = fmaf(v4.z, c[8], r1);
    r1 = fmaf(v4.w, c[9], r1);

    const float bias = c[10];
    if (active) {
        __stcs(out2 + t, make_float2(r0 + bias, r1 + bias));
    }
}

extern "C" void kernel_launch(void* const* d_in, const int* in_sizes, int n_in,
                              void* d_out, int out_size) {
    const float* x = (const float*)d_in[0];   // [B, 10]
    const float* W = (const float*)d_in[1];   // [10, 1, 10]
    const float* b = (const float*)d_in[2];   // [10, 1]

    int B = in_sizes[0] / 10;                 // 4,000,000
    int npairs = B / 2;                       // B is even

    int threads = 256;
    int blocks = (npairs + threads - 1) / threads;
    forest_warpsmem_kernel<<<blocks, threads>>>(
        (const float4*)x, W, b, (float2*)d_out, npairs);
}

// round 7
// speedup vs baseline: 1.0667x; 1.0667x over previous
#include <cuda_runtime.h>

// out[r] = dot(x[r], w_avg) + b_avg   (mean of linear == linear of mean)
//
// Single fused kernel, built strictly from measured-good elements:
//  - 5x float4 x-loads issued FIRST, plain caching (R1's best stream: 74% DRAM)
//  - per-warp param reduction + __syncwarp only (no CTA-wide BAR coupling)
//  - coefficients moved smem -> REGISTERS via 3x LDS.128 (R6's 20 scalar
//    LDS-in-FMA-chain choked MIO; 3 vector LDS is ~85% fewer MIO slots)
//  - FMA chain entirely register-resident, predicated plain float2 store
// One thread per ROW PAIR (80B = 5 x float4, 16B aligned), full grid.

__global__ __launch_bounds__(256) void forest_r7_kernel(
    const float4* __restrict__ x4,   // x as float4; 5 per row-pair
    const float*  __restrict__ W,    // [10, 1, 10]
    const float*  __restrict__ b,    // [10, 1]
    float2* __restrict__ out2,       // out as float2; 1 per row-pair
    int npairs) {
    __shared__ __align__(16) float sc[8][12];   // per-warp: c0..c9, bias, pad

    const int warp = threadIdx.x >> 5;
    const int lane = threadIdx.x & 31;

    const int t = blockIdx.x * blockDim.x + threadIdx.x;
    const bool active = (t < npairs);
    const int tc = active ? t : (npairs - 1);   // clamp tail

    // ---- 1. x loads first: out to DRAM immediately (~600cyc to hide) ----
    const float4* p = x4 + (size_t)tc * 5;
    float4 v0 = p[0];
    float4 v1 = p[1];
    float4 v2 = p[2];
    float4 v3 = p[3];
    float4 v4 = p[4];

    // ---- 2. per-warp param reduction (440B, L1-hit), overlaps x latency ----
    if (lane < 11) {
        float s = 0.f;
        if (lane < 10) {
#pragma unroll
            for (int e = 0; e < 10; ++e) s += W[e * 10 + lane];
        } else {
#pragma unroll
            for (int e = 0; e < 10; ++e) s += b[e];
        }
        sc[warp][lane] = s * 0.1f;
    }
    __syncwarp();   // warp-local (~23cyc), no cross-warp coupling

    // ---- 3. coefs smem -> registers: 3 x LDS.128 (minimal MIO traffic) ----
    const float4 ca = *reinterpret_cast<const float4*>(&sc[warp][0]); // c0..c3
    const float4 cb = *reinterpret_cast<const float4*>(&sc[warp][4]); // c4..c7
    const float4 cd = *reinterpret_cast<const float4*>(&sc[warp][8]); // c8,c9,bias,pad

    // Row 0 = {v0.xyzw, v1.xyzw, v2.xy}
    float r0 = v0.x * ca.x;
    r0 = fmaf(v0.y, ca.y, r0);
    r0 = fmaf(v0.z, ca.z, r0);
    r0 = fmaf(v0.w, ca.w, r0);
    r0 = fmaf(v1.x, cb.x, r0);
    r0 = fmaf(v1.y, cb.y, r0);
    r0 = fmaf(v1.z, cb.z, r0);
    r0 = fmaf(v1.w, cb.w, r0);
    r0 = fmaf(v2.x, cd.x, r0);
    r0 = fmaf(v2.y, cd.y, r0);

    // Row 1 = {v2.zw, v3.xyzw, v4.xyzw}
    float r1 = v2.z * ca.x;
    r1 = fmaf(v2.w, ca.y, r1);
    r1 = fmaf(v3.x, ca.z, r1);
    r1 = fmaf(v3.y, ca.w, r1);
    r1 = fmaf(v3.z, cb.x, r1);
    r1 = fmaf(v3.w, cb.y, r1);
    r1 = fmaf(v4.x, cb.z, r1);
    r1 = fmaf(v4.y, cb.w, r1);
    r1 = fmaf(v4.z, cd.x, r1);
    r1 = fmaf(v4.w, cd.y, r1);

    if (active) {
        out2[t] = make_float2(r0 + cd.z, r1 + cd.z);
    }
}

extern "C" void kernel_launch(void* const* d_in, const int* in_sizes, int n_in,
                              void* d_out, int out_size) {
    const float* x = (const float*)d_in[0];   // [B, 10]
    const float* W = (const float*)d_in[1];   // [10, 1, 10]
    const float* b = (const float*)d_in[2];   // [10, 1]

    int B = in_sizes[0] / 10;                 // 4,000,000
    int npairs = B / 2;                       // B is even

    int threads = 256;
    int blocks = (npairs + threads - 1) / threads;
    forest_r7_kernel<<<blocks, threads>>>(
        (const float4*)x, W, b, (float2*)d_out, npairs);
}